// round 10
// baseline (speedup 1.0000x reference)
#include <cuda_runtime.h>
#include <cuda_bf16.h>
#include <cstdint>
#include <cstddef>

#define HID 96
#define G3  288      // 3*H
#define TT  512
#define BB  512
#define II  100
#define BC  8        // batch elements per recurrence CTA
#define MM  (TT * BB)
#define KPU 112      // padded K used by MMA (7 x k16)
#define PBM 128      // proj M tile
#define AST 120      // smem k-stride in halves (conflict-free)

// Scratch: input projections [dir][t*B + b][3H]
__device__ float g_xp[(size_t)2 * MM * G3];
// Pre-split bf16 weights: [dir][term][288][112]
__device__ __nv_bfloat16 g_wb[(size_t)2 * 2 * G3 * KPU];
// Pre-split bf16 inputs: [term][M][112]
__device__ __nv_bfloat16 g_xb[(size_t)2 * MM * KPU];

// ---------- packed fp32x2 helpers ----------
__device__ __forceinline__ unsigned long long pk2(float lo, float hi) {
    unsigned long long r;
    asm("mov.b64 %0, {%1, %2};" : "=l"(r) : "f"(lo), "f"(hi));
    return r;
}
__device__ __forceinline__ void upk2(unsigned long long v, float& lo, float& hi) {
    asm("mov.b64 {%0, %1}, %2;" : "=f"(lo), "=f"(hi) : "l"(v));
}
__device__ __forceinline__ unsigned long long fma2(unsigned long long a,
                                                   unsigned long long b,
                                                   unsigned long long c) {
    unsigned long long d;
    asm("fma.rn.f32x2 %0, %1, %2, %3;" : "=l"(d) : "l"(a), "l"(b), "l"(c));
    return d;
}
__device__ __forceinline__ float sigmoidf_(float x) {
    return __fdividef(1.f, 1.f + __expf(-x));
}
__device__ __forceinline__ float tanhf_(float x) {
    float e = __expf(-2.f * fabsf(x));
    float t = __fdividef(1.f - e, 1.f + e);
    return copysignf(t, x);
}
__device__ __forceinline__ void mma16816(float* c, const uint32_t* a, const uint32_t* b) {
    asm volatile(
        "mma.sync.aligned.m16n8k16.row.col.f32.bf16.bf16.f32 "
        "{%0,%1,%2,%3}, {%4,%5,%6,%7}, {%8,%9}, {%0,%1,%2,%3};"
        : "+f"(c[0]), "+f"(c[1]), "+f"(c[2]), "+f"(c[3])
        : "r"(a[0]), "r"(a[1]), "r"(a[2]), "r"(a[3]), "r"(b[0]), "r"(b[1]));
}

// =====================================================================
// Kernel W: W_ih -> bf16 hi/lo, K padded to 112
// =====================================================================
__global__ void wconv_kernel(const float* __restrict__ wf, const float* __restrict__ wb)
{
    int idx = blockIdx.x * 256 + threadIdx.x;
    if (idx >= 2 * G3 * KPU) return;
    int dir = idx / (G3 * KPU);
    int rem = idx - dir * (G3 * KPU);
    int n = rem / KPU, k = rem - n * KPU;
    const float* w = dir ? wb : wf;
    float v = (k < II) ? w[n * II + k] : 0.f;
    __nv_bfloat16 h = __float2bfloat16(v);
    __nv_bfloat16 l = __float2bfloat16(v - __bfloat162float(h));
    g_wb[((size_t)dir * 2 + 0) * G3 * KPU + rem] = h;
    g_wb[((size_t)dir * 2 + 1) * G3 * KPU + rem] = l;
}

// =====================================================================
// Kernel X: x -> bf16 hi/lo, [term][M][112]
// =====================================================================
__global__ void xconv_kernel(const float* __restrict__ x)
{
    int idx = blockIdx.x * 256 + threadIdx.x;
    if (idx >= MM * KPU) return;
    int r = idx / KPU, k = idx - r * KPU;
    float v = (k < II) ? x[(size_t)r * II + k] : 0.f;
    __nv_bfloat16 h = __float2bfloat16(v);
    __nv_bfloat16 l = __float2bfloat16(v - __bfloat162float(h));
    g_xb[idx] = h;
    g_xb[(size_t)MM * KPU + idx] = l;
}

// =====================================================================
// Kernel A: projection GEMM via mma.sync bf16 (3-term split, fp32 accum)
//   At the legacy-HMMA roofline (~32 cyc/SMSP per m16n8k16) — unchanged.
// =====================================================================
#define SA0 0                      // A hi: 128*120*2 = 30720 B
#define SA1 30720                  // A lo
#define SB0 61440                  // B hi: 96*120*2 = 23040 B
#define SB1 84480                  // B lo
#define SBIAS 107520               // 96 floats
#define SMTOT (107520 + 96 * 4)

__global__ void __launch_bounds__(256) proj_mma_kernel(
    const float* __restrict__ b_ih_f, const float* __restrict__ b_ih_b)
{
    extern __shared__ char smp[];
    const int tid = threadIdx.x, wid = tid >> 5, lid = tid & 31;
    const int dir = blockIdx.z;
    const int ny = blockIdx.y;                 // N-block (3 x 96)
    const size_t row0 = (size_t)blockIdx.x * PBM;
    const float* bias = dir ? b_ih_b : b_ih_f;
    float* bsm = (float*)(smp + SBIAS);

    if (tid < 96) bsm[tid] = bias[ny * 96 + tid];

    // Fill A: 2 terms x 128 rows x 14 uint4 = 3584 copies
    for (int idx = tid; idx < 3584; idx += 256) {
        int term = idx / 1792;
        int rem = idx - term * 1792;
        int r = rem / 14, k8 = (rem - r * 14) * 8;
        uint4 v = *(const uint4*)&g_xb[((size_t)term * MM + row0 + r) * KPU + k8];
        *(uint4*)((__nv_bfloat16*)(smp + (term ? SA1 : SA0)) + r * AST + k8) = v;
    }
    // Fill B: 2 terms x 96 rows x 14 uint4 = 2688 copies
    for (int idx = tid; idx < 2688; idx += 256) {
        int term = idx / 1344;
        int rem = idx - term * 1344;
        int n = rem / 14, k8 = (rem - n * 14) * 8;
        uint4 v = *(const uint4*)&g_wb[(((size_t)dir * 2 + term) * G3 + ny * 96 + n) * KPU + k8];
        *(uint4*)((__nv_bfloat16*)(smp + (term ? SB1 : SB0)) + n * AST + k8) = v;
    }
    __syncthreads();

    const int wm = wid & 3, wn = wid >> 2;
    const int m0 = wm * 32, n0 = wn * 48;
    const int gid = lid >> 2, tig = lid & 3;

    float acc[2][6][4];
#pragma unroll
    for (int i = 0; i < 2; i++)
#pragma unroll
        for (int j = 0; j < 6; j++)
#pragma unroll
            for (int q = 0; q < 4; q++) acc[i][j][q] = 0.f;

#pragma unroll 1
    for (int term = 0; term < 3; term++) {
        const __nv_bfloat16* As = (const __nv_bfloat16*)(smp + (term == 2 ? SA1 : SA0));
        const __nv_bfloat16* Bs = (const __nv_bfloat16*)(smp + (term == 1 ? SB1 : SB0));
#pragma unroll
        for (int ks = 0; ks < 7; ks++) {
            const int kk = ks * 16 + tig * 2;
            uint32_t a[2][4], b[6][2];
#pragma unroll
            for (int i = 0; i < 2; i++) {
                int r = m0 + i * 16 + gid;
                a[i][0] = *(const uint32_t*)&As[r * AST + kk];
                a[i][1] = *(const uint32_t*)&As[(r + 8) * AST + kk];
                a[i][2] = *(const uint32_t*)&As[r * AST + kk + 8];
                a[i][3] = *(const uint32_t*)&As[(r + 8) * AST + kk + 8];
            }
#pragma unroll
            for (int j = 0; j < 6; j++) {
                int n = n0 + j * 8 + gid;
                b[j][0] = *(const uint32_t*)&Bs[n * AST + kk];
                b[j][1] = *(const uint32_t*)&Bs[n * AST + kk + 8];
            }
#pragma unroll
            for (int i = 0; i < 2; i++)
#pragma unroll
                for (int j = 0; j < 6; j++)
                    mma16816(acc[i][j], a[i], b[j]);
        }
    }

    // Epilogue: add bias, write g_xp
#pragma unroll
    for (int i = 0; i < 2; i++) {
        size_t r = row0 + m0 + i * 16 + gid;
        size_t gb0 = ((size_t)dir * MM + r) * G3;
        size_t gb1 = gb0 + 8 * G3;
#pragma unroll
        for (int j = 0; j < 6; j++) {
            int bn = n0 + j * 8 + tig * 2;
            float bz0 = bsm[bn], bz1 = bsm[bn + 1];
            int g = ny * 96 + bn;
            *(float2*)&g_xp[gb0 + g] = make_float2(acc[i][j][0] + bz0, acc[i][j][1] + bz1);
            *(float2*)&g_xp[gb1 + g] = make_float2(acc[i][j][2] + bz0, acc[i][j][3] + bz1);
        }
    }
}

// =====================================================================
// Kernel B: GRU recurrence. CTA = (dir, 8 batch), 1024 threads (legal!).
//   Thread (g = tid>>2 in 0..255, q = tid&3) holds 24 W_hh weights;
//   quarter-dots reduced by 2x shfl.bfly (q = lane bits [0:2]).
//   Rows 256..287: tail work on warps 28..31 (tid >= 896, one per SMSP,
//   highest arbiter priority) reusing the SAME h-slice — no extra LDS.
//   x_proj prefetched from HBM at step top; no smem staging.
// =====================================================================
__global__ void __launch_bounds__(1024, 1) gru_scan_kernel(
    const float* __restrict__ w_hh_f, const float* __restrict__ b_hh_f,
    const float* __restrict__ w_hh_b, const float* __restrict__ b_hh_b,
    float* __restrict__ out)
{
    __shared__ __align__(16) float hs [2][BC][HID];   // 6 KB
    __shared__ __align__(16) float hps[BC][G3];       // 9 KB (final dots)
    __shared__ float bhs[G3];

    const int tid  = threadIdx.x;
    const int dir  = blockIdx.y;
    const int b0   = blockIdx.x * BC;
    const float* whh = dir ? w_hh_b : w_hh_f;
    const float* bhh = dir ? b_hh_b : b_hh_f;

    const int g = tid >> 2;      // 0..255
    const int q = tid & 3;       // 0..3
    const bool tail = (tid >= 896);
    const int g2 = 256 + ((tid - 896) >> 2);   // 256..287 (tail threads)

    // Main 24 weights -> 12 packed f32x2
    unsigned long long w2[12];
    {
        const float4* wr = (const float4*)(whh + (size_t)g * HID + q * 24);
#pragma unroll
        for (int j = 0; j < 6; j++) {
            float4 f = wr[j];
            w2[2 * j]     = pk2(f.x, f.y);
            w2[2 * j + 1] = pk2(f.z, f.w);
        }
    }
    // Tail 24 weights (warps 28..31 only)
    unsigned long long w2t[12];
    if (tail) {
        const float4* wr = (const float4*)(whh + (size_t)g2 * HID + q * 24);
#pragma unroll
        for (int j = 0; j < 6; j++) {
            float4 f = wr[j];
            w2t[2 * j]     = pk2(f.x, f.y);
            w2t[2 * j + 1] = pk2(f.z, f.w);
        }
    }
    if (tid < G3) bhs[tid] = bhh[tid];
    for (int i = tid; i < BC * HID; i += 1024) ((float*)hs[0])[i] = 0.f;
    __syncthreads();

    // Phase-2 identity (fixed): unit = (b, j), valid when tid < 768
    const int p2b = tid / HID, p2j = tid - p2b * HID;

    for (int s = 0; s < TT; s++) {
        const int cur = s & 1, nxt = cur ^ 1;
        const int tt = dir ? (TT - 1 - s) : s;

        // Prefetch this step's x_proj (consumed in phase 2, far later)
        float xr = 0.f, xz = 0.f, xn = 0.f;
        if (tid < BC * HID) {
            const float* xpp = g_xp +
                ((size_t)dir * MM + (size_t)tt * BB + (b0 + p2b)) * G3 + p2j;
            xr = xpp[0];
            xz = xpp[96];
            xn = xpp[192];
        }

        // Phase 1: quarter-dots + butterfly reduce -> hps[b][*] (final)
#pragma unroll
        for (int b = 0; b < BC; b++) {
            const ulonglong2* h2 = (const ulonglong2*)(&hs[cur][b][q * 24]);
            ulonglong2 h0 = h2[0], h1 = h2[1], h2v = h2[2];
            ulonglong2 h3 = h2[3], h4 = h2[4], h5 = h2[5];

            unsigned long long a0, a1;
            a0 = fma2(w2[0],  h0.x, 0ull);  a1 = fma2(w2[1],  h0.y, 0ull);
            a0 = fma2(w2[2],  h1.x, a0);    a1 = fma2(w2[3],  h1.y, a1);
            a0 = fma2(w2[4],  h2v.x, a0);   a1 = fma2(w2[5],  h2v.y, a1);
            a0 = fma2(w2[6],  h3.x, a0);    a1 = fma2(w2[7],  h3.y, a1);
            a0 = fma2(w2[8],  h4.x, a0);    a1 = fma2(w2[9],  h4.y, a1);
            a0 = fma2(w2[10], h5.x, a0);    a1 = fma2(w2[11], h5.y, a1);
            float p0, p1, p2, p3;
            upk2(a0, p0, p1); upk2(a1, p2, p3);
            float p = (p0 + p1) + (p2 + p3);
            p += __shfl_xor_sync(0xffffffffu, p, 1);
            p += __shfl_xor_sync(0xffffffffu, p, 2);
            if (q == 0) hps[b][g] = p;

            if (tail) {   // second dot: same h-slice, tail weight row
                unsigned long long c0, c1;
                c0 = fma2(w2t[0],  h0.x, 0ull);  c1 = fma2(w2t[1],  h0.y, 0ull);
                c0 = fma2(w2t[2],  h1.x, c0);    c1 = fma2(w2t[3],  h1.y, c1);
                c0 = fma2(w2t[4],  h2v.x, c0);   c1 = fma2(w2t[5],  h2v.y, c1);
                c0 = fma2(w2t[6],  h3.x, c0);    c1 = fma2(w2t[7],  h3.y, c1);
                c0 = fma2(w2t[8],  h4.x, c0);    c1 = fma2(w2t[9],  h4.y, c1);
                c0 = fma2(w2t[10], h5.x, c0);    c1 = fma2(w2t[11], h5.y, c1);
                float t0, t1, t2, t3;
                upk2(c0, t0, t1); upk2(c1, t2, t3);
                float pt = (t0 + t1) + (t2 + t3);
                pt += __shfl_xor_sync(0xffffffffu, pt, 1);
                pt += __shfl_xor_sync(0xffffffffu, pt, 2);
                if (q == 0) hps[b][g2] = pt;
            }
        }
        __syncthreads();

        // Phase 2: gates + state update (768 units, single pass)
        if (tid < BC * HID) {
            float hpr = hps[p2b][p2j]       + bhs[p2j];
            float hpz = hps[p2b][p2j + 96]  + bhs[p2j + 96];
            float hpn = hps[p2b][p2j + 192] + bhs[p2j + 192];
            float r = sigmoidf_(xr + hpr);
            float z = sigmoidf_(xz + hpz);
            float n = tanhf_  (xn + r * hpn);
            float hn = (1.f - z) * n + z * hs[cur][p2b][p2j];
            hs[nxt][p2b][p2j] = hn;
            out[((size_t)tt * BB + (b0 + p2b)) * (2 * HID) + dir * HID + p2j] = hn;
        }
        __syncthreads();
    }
}

// =====================================================================
extern "C" void kernel_launch(void* const* d_in, const int* in_sizes, int n_in,
                              void* d_out, int out_size)
{
    const float* x      = (const float*)d_in[0];
    const float* w_ih_f = (const float*)d_in[1];
    const float* w_hh_f = (const float*)d_in[2];
    const float* b_ih_f = (const float*)d_in[3];
    const float* b_hh_f = (const float*)d_in[4];
    const float* w_ih_b = (const float*)d_in[5];
    const float* w_hh_b = (const float*)d_in[6];
    const float* b_ih_b = (const float*)d_in[7];
    const float* b_hh_b = (const float*)d_in[8];
    float* out = (float*)d_out;

    wconv_kernel<<<(2 * G3 * KPU + 255) / 256, 256>>>(w_ih_f, w_ih_b);
    xconv_kernel<<<(MM * KPU + 255) / 256, 256>>>(x);

    cudaFuncSetAttribute(proj_mma_kernel,
                         cudaFuncAttributeMaxDynamicSharedMemorySize, SMTOT);
    dim3 gA(MM / PBM, 3, 2);                 // (2048, 3, 2)
    proj_mma_kernel<<<gA, 256, SMTOT>>>(b_ih_f, b_ih_b);

    dim3 gB(BB / BC, 2);                     // 128 CTAs, one wave
    gru_scan_kernel<<<gB, 1024>>>(w_hh_f, b_hh_f, w_hh_b, b_hh_b, out);
}